// round 1
// baseline (speedup 1.0000x reference)
#include <cuda_runtime.h>
#include <math.h>

#define B   512
#define D   512
#define NC  1000
#define MM  200
#define KP  50
#define KN  20
#define NCK (NC*KP)         // 50000
#define TEMPF   0.07f
#define MARGINF 0.5f

// ---------------- device scratch (allocation-free rule: __device__ globals) -----------
__device__ float g_f[B*D];                 // normalized features
__device__ int   g_rank[B], g_gsize[B], g_first[B];
__device__ int   g_ov[NCK];                // override: batch row index or -1
__device__ float g_pos[B], g_all[B], g_hard[B], g_posb[B];
__device__ int   g_hcnt[B], g_cntb[B];

// ---------------- init: reset override table + accumulators every replay --------------
__global__ void k_init() {
    int i = blockIdx.x * blockDim.x + threadIdx.x;
    if (i < NCK) g_ov[i] = -1;
    if (i < B) {
        g_pos[i] = 0.f; g_all[i] = 0.f; g_hard[i] = 0.f; g_posb[i] = 0.f;
        g_hcnt[i] = 0;  g_cntb[i] = 0;
    }
}

// ---------------- L2 normalize rows ---------------------------------------------------
__global__ void k_norm(const float* __restrict__ x) {
    int row = blockIdx.x;
    const float* xr = x + (size_t)row * D;
    float s = 0.f;
    for (int i = threadIdx.x; i < D; i += blockDim.x) { float v = xr[i]; s += v * v; }
    __shared__ float sm[8];
    #pragma unroll
    for (int o = 16; o; o >>= 1) s += __shfl_xor_sync(0xffffffffu, s, o);
    if ((threadIdx.x & 31) == 0) sm[threadIdx.x >> 5] = s;
    __syncthreads();
    if (threadIdx.x == 0) {
        float t = 0.f;
        for (int w = 0; w < (int)(blockDim.x >> 5); w++) t += sm[w];
        sm[0] = t;
    }
    __syncthreads();
    float inv = 1.f / fmaxf(sqrtf(sm[0]), 1e-12f);
    for (int i = threadIdx.x; i < D; i += blockDim.x)
        g_f[(size_t)row * D + i] = xr[i] * inv;
}

// ---------------- label stats + override table ----------------------------------------
__global__ void k_stats(const int* __restrict__ labels, const int* __restrict__ memptr) {
    __shared__ int lab[B];
    int i = threadIdx.x;
    lab[i] = labels[i];
    __syncthreads();
    int li = lab[i];
    int r = 0, gs = 0, fi = B;
    for (int j = 0; j < B; j++) {
        if (lab[j] == li) { gs++; r += (j < i); if (j < fi) fi = j; }
    }
    g_rank[i] = r; g_gsize[i] = gs; g_first[i] = fi;
    int wp = (memptr[li] + r) % MM;
    if (wp < KP) g_ov[li * KP + wp] = i;   // unique (lab,wp) pairs -> no race
}

// ---------------- in-batch positive term ----------------------------------------------
__global__ void k_batch(const int* __restrict__ labels) {
    int i = blockIdx.x;
    __shared__ float fi[D];
    __shared__ float ssum[128];
    __shared__ int   scnt[128];
    for (int t = threadIdx.x; t < D; t += blockDim.x) fi[t] = g_f[(size_t)i * D + t];
    __syncthreads();
    int li = labels[i];
    int fidx = g_first[i];
    int gs = g_gsize[i];
    float s = 0.f; int cnt = 0;
    if (gs > 1) {
        for (int j = threadIdx.x; j < B; j += blockDim.x) {
            if (labels[j] == li && g_rank[j] != fidx) {
                float d = 0.f;
                const float* fj = g_f + (size_t)j * D;
                for (int t = 0; t < D; t++) d += fi[t] * fj[t];
                s += d / TEMPF; cnt++;
            }
        }
    }
    ssum[threadIdx.x] = s; scnt[threadIdx.x] = cnt;
    __syncthreads();
    for (int o = 64; o; o >>= 1) {
        if ((int)threadIdx.x < o) { ssum[threadIdx.x] += ssum[threadIdx.x + o]; scnt[threadIdx.x] += scnt[threadIdx.x + o]; }
        __syncthreads();
    }
    if (threadIdx.x == 0) { g_posb[i] = ssum[0]; g_cntb[i] = scnt[0]; }
}

// ---------------- fused GEMM + contrastive epilogue -----------------------------------
// C[b, ck] = dot(f[b], Brow(ck)) / TEMP, ck = c*KP+k, Brow overridden by g_f[ov] if set.
// Epilogue: c==lab[b] -> pos ; else k<KN -> all (+hard if > MARGIN). S never stored.
#define BM 128
#define BN 64
#define BK 16
#define PADA 4
#define PADB 1

__global__ __launch_bounds__(256, 2)
void k_gemm(const float* __restrict__ memb, const int* __restrict__ labels) {
    __shared__ float As[BK][BM + PADA];
    __shared__ float Bs[BK][BN + PADB];
    __shared__ const float* rowp[BN];
    __shared__ float smPos[BM], smAll[BM], smHard[BM];
    __shared__ int   smHc[BM];

    int bm = blockIdx.y * BM;
    int bn = blockIdx.x * BN;
    int tid = threadIdx.x;
    int tx = tid & 15, ty = tid >> 4;

    if (tid < BN) {
        int ck = bn + tid;
        const float* p = g_f;                        // safe dummy for OOB rows
        if (ck < NCK) {
            int ov = g_ov[ck];
            if (ov >= 0) p = g_f + (size_t)ov * D;
            else {
                int c = ck / KP, kk = ck - c * KP;
                p = memb + ((size_t)c * MM + kk) * D;
            }
        }
        rowp[tid] = p;
    }
    if (tid < BM) { smPos[tid] = 0.f; smAll[tid] = 0.f; smHard[tid] = 0.f; smHc[tid] = 0; }
    __syncthreads();

    int lr = tid >> 2;          // 0..63
    int lc = (tid & 3) * 4;     // 0,4,8,12
    const float* A0 = g_f + (size_t)(bm + lr) * D + lc;
    const float* A1 = g_f + (size_t)(bm + lr + 64) * D + lc;
    const float* Bp = rowp[lr] + lc;

    float acc[8][4];
    #pragma unroll
    for (int i = 0; i < 8; i++)
        #pragma unroll
        for (int j = 0; j < 4; j++) acc[i][j] = 0.f;

    for (int k0 = 0; k0 < D; k0 += BK) {
        float4 a0 = *(const float4*)(A0 + k0);
        float4 a1 = *(const float4*)(A1 + k0);
        float4 b0 = *(const float4*)(Bp + k0);
        __syncthreads();
        As[lc + 0][lr] = a0.x; As[lc + 1][lr] = a0.y; As[lc + 2][lr] = a0.z; As[lc + 3][lr] = a0.w;
        As[lc + 0][lr + 64] = a1.x; As[lc + 1][lr + 64] = a1.y; As[lc + 2][lr + 64] = a1.z; As[lc + 3][lr + 64] = a1.w;
        Bs[lc + 0][lr] = b0.x; Bs[lc + 1][lr] = b0.y; Bs[lc + 2][lr] = b0.z; Bs[lc + 3][lr] = b0.w;
        __syncthreads();
        #pragma unroll
        for (int kk = 0; kk < BK; kk++) {
            float av[8], bv[4];
            #pragma unroll
            for (int i = 0; i < 8; i++) av[i] = As[kk][tx * 8 + i];
            #pragma unroll
            for (int j = 0; j < 4; j++) bv[j] = Bs[kk][ty * 4 + j];
            #pragma unroll
            for (int i = 0; i < 8; i++)
                #pragma unroll
                for (int j = 0; j < 4; j++) acc[i][j] += av[i] * bv[j];
        }
    }

    // epilogue: fuse contrastive reductions
    #pragma unroll
    for (int i = 0; i < 8; i++) {
        int b = bm + tx * 8 + i;
        int lb = labels[b];
        float pos = 0.f, alls = 0.f, hard = 0.f; int hc = 0;
        #pragma unroll
        for (int j = 0; j < 4; j++) {
            int ck = bn + ty * 4 + j;
            if (ck >= NCK) continue;
            float s = acc[i][j] / TEMPF;
            int c = ck / KP; int kk = ck - c * KP;
            if (c == lb) {
                pos += s;
            } else if (kk < KN) {
                alls += s;
                if (s > MARGINF) { hard += s; hc++; }
            }
        }
        int m = tx * 8 + i;
        if (pos  != 0.f) atomicAdd(&smPos[m],  pos);   // adding 0 == skipping 0
        if (alls != 0.f) atomicAdd(&smAll[m],  alls);
        if (hard != 0.f) atomicAdd(&smHard[m], hard);
        if (hc)          atomicAdd(&smHc[m],   hc);
    }
    __syncthreads();
    if (tid < BM) {
        int b = bm + tid;
        if (smPos[tid]  != 0.f) atomicAdd(&g_pos[b],  smPos[tid]);
        if (smAll[tid]  != 0.f) atomicAdd(&g_all[b],  smAll[tid]);
        if (smHard[tid] != 0.f) atomicAdd(&g_hard[b], smHard[tid]);
        if (smHc[tid])          atomicAdd(&g_hcnt[b], smHc[tid]);
    }
}

// ---------------- final combine -------------------------------------------------------
__global__ void k_final(float* __restrict__ out) {
    __shared__ float sm[B];
    int i = threadIdx.x;
    float pos_sum = g_posb[i] + g_pos[i];
    float pos_cnt = (float)(g_cntb[i] + KP);
    float pl = -pos_sum / pos_cnt;
    int hc = g_hcnt[i];
    float nl = (hc > 0) ? (g_hard[i] / (float)(hc > 1 ? hc : 1))
                        : (g_all[i] / (float)((NC - 1) * KN));
    sm[i] = pl + nl;
    __syncthreads();
    for (int o = 256; o; o >>= 1) {
        if (i < o) sm[i] += sm[i + o];
        __syncthreads();
    }
    if (i == 0) out[0] = sm[0] / (float)B;
}

// ---------------- launch --------------------------------------------------------------
extern "C" void kernel_launch(void* const* d_in, const int* in_sizes, int n_in,
                              void* d_out, int out_size) {
    const float* features = (const float*)d_in[0];
    const int*   labels   = (const int*)d_in[1];
    const float* memb     = (const float*)d_in[2];
    const int*   memptr   = (const int*)d_in[3];
    float* out = (float*)d_out;

    k_init<<<(NCK + 255) / 256, 256>>>();
    k_norm<<<B, 256>>>(features);
    k_stats<<<1, B>>>(labels, memptr);
    k_batch<<<B, 128>>>(labels);
    dim3 grid((NCK + BN - 1) / BN, B / BM);
    k_gemm<<<grid, 256>>>(memb, labels);
    k_final<<<1, B>>>(out);
}

// round 2
// speedup vs baseline: 2.3401x; 2.3401x over previous
#include <cuda_runtime.h>
#include <math.h>
#include <stdint.h>

#define B   512
#define D   512
#define NC  1000
#define MM  200
#define KP  50
#define KN  20
#define NCK (NC*KP)         // 50000
#define TEMPF   0.07f
#define MARGINF 0.5f

// ---------------- device scratch (allocation-free rule: __device__ globals) -----------
__device__ float g_f[B*D];                 // normalized features
__device__ int   g_rank[B], g_gsize[B], g_first[B];
__device__ int   g_ov[NCK];                // override: batch row index or -1
__device__ float g_pos[B], g_all[B], g_hard[B], g_posb[B];
__device__ int   g_hcnt[B], g_cntb[B];

// ---------------- init: reset override table + accumulators every replay --------------
__global__ void k_init() {
    int i = blockIdx.x * blockDim.x + threadIdx.x;
    if (i < NCK) g_ov[i] = -1;
    if (i < B) {
        g_pos[i] = 0.f; g_all[i] = 0.f; g_hard[i] = 0.f; g_posb[i] = 0.f;
        g_hcnt[i] = 0;  g_cntb[i] = 0;
    }
}

// ---------------- L2 normalize rows ---------------------------------------------------
__global__ void k_norm(const float* __restrict__ x) {
    int row = blockIdx.x;
    const float* xr = x + (size_t)row * D;
    float s = 0.f;
    for (int i = threadIdx.x; i < D; i += blockDim.x) { float v = xr[i]; s += v * v; }
    __shared__ float sm[8];
    #pragma unroll
    for (int o = 16; o; o >>= 1) s += __shfl_xor_sync(0xffffffffu, s, o);
    if ((threadIdx.x & 31) == 0) sm[threadIdx.x >> 5] = s;
    __syncthreads();
    if (threadIdx.x == 0) {
        float t = 0.f;
        for (int w = 0; w < (int)(blockDim.x >> 5); w++) t += sm[w];
        sm[0] = t;
    }
    __syncthreads();
    float inv = 1.f / fmaxf(sqrtf(sm[0]), 1e-12f);
    for (int i = threadIdx.x; i < D; i += blockDim.x)
        g_f[(size_t)row * D + i] = xr[i] * inv;
}

// ---------------- label stats + override table ----------------------------------------
__global__ void k_stats(const int* __restrict__ labels, const int* __restrict__ memptr) {
    __shared__ int lab[B];
    int i = threadIdx.x;
    lab[i] = labels[i];
    __syncthreads();
    int li = lab[i];
    int r = 0, gs = 0, fi = B;
    for (int j = 0; j < B; j++) {
        if (lab[j] == li) { gs++; r += (j < i); if (j < fi) fi = j; }
    }
    g_rank[i] = r; g_gsize[i] = gs; g_first[i] = fi;
    int wp = (memptr[li] + r) % MM;
    if (wp < KP) g_ov[li * KP + wp] = i;   // unique (lab,wp) pairs -> no race
}

// ---------------- in-batch positive term ----------------------------------------------
__global__ void k_batch(const int* __restrict__ labels) {
    int i = blockIdx.x;
    if (g_gsize[i] <= 1) return;           // most blocks exit here (g_posb/cntb pre-zeroed)
    __shared__ float fi[D];
    __shared__ float ssum[128];
    __shared__ int   scnt[128];
    for (int t = threadIdx.x; t < D; t += blockDim.x) fi[t] = g_f[(size_t)i * D + t];
    __syncthreads();
    int li = labels[i];
    int fidx = g_first[i];
    float s = 0.f; int cnt = 0;
    for (int j = threadIdx.x; j < B; j += blockDim.x) {
        if (labels[j] == li && g_rank[j] != fidx) {
            float d = 0.f;
            const float* fj = g_f + (size_t)j * D;
            for (int t = 0; t < D; t++) d += fi[t] * fj[t];
            s += d / TEMPF; cnt++;
        }
    }
    ssum[threadIdx.x] = s; scnt[threadIdx.x] = cnt;
    __syncthreads();
    for (int o = 64; o; o >>= 1) {
        if ((int)threadIdx.x < o) { ssum[threadIdx.x] += ssum[threadIdx.x + o]; scnt[threadIdx.x] += scnt[threadIdx.x + o]; }
        __syncthreads();
    }
    if (threadIdx.x == 0) { g_posb[i] = ssum[0]; g_cntb[i] = scnt[0]; }
}

// ---------------- tf32 tensor-core GEMM + fused contrastive epilogue ------------------
// C[b, ck] = dot(f[b], Brow(ck)) / TEMP, with Brow overridden by g_f[ov] when set.
#define BM 128
#define BN 64
#define BK 16
#define LDS_A 20           // BK + 4 pad: bank = (20*row + k) % 32 is conflict-free

__device__ __forceinline__ uint32_t f2tf32(float x) {
    uint32_t r; asm("cvt.rna.tf32.f32 %0, %1;" : "=r"(r) : "f"(x)); return r;
}

__global__ __launch_bounds__(256, 2)
void k_gemm(const float* __restrict__ memb, const int* __restrict__ labels) {
    __shared__ uint32_t As[2][BM][LDS_A];
    __shared__ uint32_t Bs[2][BN][LDS_A];
    __shared__ const float* rowp[BN];
    __shared__ float smPos[BM], smAll[BM], smHard[BM];
    __shared__ int   smHc[BM];

    const int bm = blockIdx.y * BM;
    const int bn = blockIdx.x * BN;
    const int tid = threadIdx.x;
    const int lane = tid & 31, warp = tid >> 5;
    const int wm = (warp >> 2) * 64;    // warp m offset (0/64)
    const int wn = (warp & 3) * 16;     // warp n offset (0/16/32/48)
    const int g  = lane >> 2;           // groupID
    const int tg = lane & 3;            // thread-in-group

    if (tid < BN) {
        int ck = bn + tid;
        const float* p = g_f;                        // safe dummy for OOB ck
        if (ck < NCK) {
            int ov = g_ov[ck];
            if (ov >= 0) p = g_f + (size_t)ov * D;
            else {
                int c = ck / KP, kk = ck - c * KP;
                p = memb + ((size_t)c * MM + kk) * D;
            }
        }
        rowp[tid] = p;
    }
    if (tid < BM) { smPos[tid] = 0.f; smAll[tid] = 0.f; smHard[tid] = 0.f; smHc[tid] = 0; }
    __syncthreads();

    // global load assignment: A rows r0=tid>>2 and r0+64, f4-col c = tid&3 (k = 4c..4c+3)
    const int r0 = tid >> 2, c0 = tid & 3;
    const float* Ag0 = g_f + (size_t)(bm + r0) * D + c0 * 4;
    const float* Ag1 = Ag0 + (size_t)64 * D;
    const float* Bg  = rowp[r0] + c0 * 4;

    float4 pa0 = *(const float4*)Ag0;
    float4 pa1 = *(const float4*)Ag1;
    float4 pb  = *(const float4*)Bg;

    float acc[4][2][4];
    #pragma unroll
    for (int i = 0; i < 4; i++)
        #pragma unroll
        for (int j = 0; j < 2; j++)
            #pragma unroll
            for (int q = 0; q < 4; q++) acc[i][j][q] = 0.f;

    // store tile 0
    {
        uint32_t* pA0 = &As[0][r0][c0 * 4];
        uint32_t* pA1 = &As[0][r0 + 64][c0 * 4];
        uint32_t* pB  = &Bs[0][r0][c0 * 4];
        pA0[0]=f2tf32(pa0.x); pA0[1]=f2tf32(pa0.y); pA0[2]=f2tf32(pa0.z); pA0[3]=f2tf32(pa0.w);
        pA1[0]=f2tf32(pa1.x); pA1[1]=f2tf32(pa1.y); pA1[2]=f2tf32(pa1.z); pA1[3]=f2tf32(pa1.w);
        pB [0]=f2tf32(pb.x);  pB [1]=f2tf32(pb.y);  pB [2]=f2tf32(pb.z);  pB [3]=f2tf32(pb.w);
    }
    __syncthreads();

    const int NIT = D / BK;   // 32
    #pragma unroll 1
    for (int it = 0; it < NIT; it++) {
        int p = it & 1;
        if (it < NIT - 1) {
            int ko = (it + 1) * BK;
            pa0 = *(const float4*)(Ag0 + ko);
            pa1 = *(const float4*)(Ag1 + ko);
            pb  = *(const float4*)(Bg  + ko);
        }
        #pragma unroll
        for (int ks = 0; ks < BK; ks += 8) {
            uint32_t af[4][4], bf[2][2];
            #pragma unroll
            for (int mi = 0; mi < 4; mi++) {
                int mr = wm + mi * 16 + g;
                af[mi][0] = As[p][mr    ][ks + tg];
                af[mi][1] = As[p][mr + 8][ks + tg];
                af[mi][2] = As[p][mr    ][ks + tg + 4];
                af[mi][3] = As[p][mr + 8][ks + tg + 4];
            }
            #pragma unroll
            for (int nj = 0; nj < 2; nj++) {
                int nr = wn + nj * 8 + g;
                bf[nj][0] = Bs[p][nr][ks + tg];
                bf[nj][1] = Bs[p][nr][ks + tg + 4];
            }
            #pragma unroll
            for (int mi = 0; mi < 4; mi++)
                #pragma unroll
                for (int nj = 0; nj < 2; nj++) {
                    asm volatile(
                        "mma.sync.aligned.m16n8k8.row.col.f32.tf32.tf32.f32 "
                        "{%0,%1,%2,%3}, {%4,%5,%6,%7}, {%8,%9}, {%0,%1,%2,%3};\n"
                        : "+f"(acc[mi][nj][0]), "+f"(acc[mi][nj][1]),
                          "+f"(acc[mi][nj][2]), "+f"(acc[mi][nj][3])
                        : "r"(af[mi][0]), "r"(af[mi][1]), "r"(af[mi][2]), "r"(af[mi][3]),
                          "r"(bf[nj][0]), "r"(bf[nj][1]));
                }
        }
        if (it < NIT - 1) {
            int q = p ^ 1;
            uint32_t* pA0 = &As[q][r0][c0 * 4];
            uint32_t* pA1 = &As[q][r0 + 64][c0 * 4];
            uint32_t* pB  = &Bs[q][r0][c0 * 4];
            pA0[0]=f2tf32(pa0.x); pA0[1]=f2tf32(pa0.y); pA0[2]=f2tf32(pa0.z); pA0[3]=f2tf32(pa0.w);
            pA1[0]=f2tf32(pa1.x); pA1[1]=f2tf32(pa1.y); pA1[2]=f2tf32(pa1.z); pA1[3]=f2tf32(pa1.w);
            pB [0]=f2tf32(pb.x);  pB [1]=f2tf32(pb.y);  pB [2]=f2tf32(pb.z);  pB [3]=f2tf32(pb.w);
        }
        __syncthreads();
    }

    // ---- fused epilogue: pos / all / hard reductions (S never stored) ----
    #pragma unroll
    for (int mi = 0; mi < 4; mi++) {
        #pragma unroll
        for (int rr = 0; rr < 2; rr++) {           // rr=0 -> c0/c1 rows, rr=1 -> +8
            int ml = wm + mi * 16 + g + rr * 8;    // local row 0..127
            int lb = labels[bm + ml];
            float pos = 0.f, alls = 0.f, hard = 0.f; int hc = 0;
            #pragma unroll
            for (int nj = 0; nj < 2; nj++) {
                #pragma unroll
                for (int q = 0; q < 2; q++) {
                    int ck = bn + wn + nj * 8 + 2 * tg + q;
                    if (ck >= NCK) continue;
                    float s = acc[mi][nj][rr * 2 + q] / TEMPF;
                    unsigned c = (unsigned)ck / KP;
                    int kk = ck - (int)c * KP;
                    if ((int)c == lb) {
                        pos += s;
                    } else if (kk < KN) {
                        alls += s;
                        if (s > MARGINF) { hard += s; hc++; }
                    }
                }
            }
            if (pos  != 0.f) atomicAdd(&smPos[ml],  pos);   // adding 0 == skipping 0
            if (alls != 0.f) atomicAdd(&smAll[ml],  alls);
            if (hard != 0.f) atomicAdd(&smHard[ml], hard);
            if (hc)          atomicAdd(&smHc[ml],   hc);
        }
    }
    __syncthreads();
    if (tid < BM) {
        int b = bm + tid;
        if (smPos[tid]  != 0.f) atomicAdd(&g_pos[b],  smPos[tid]);
        if (smAll[tid]  != 0.f) atomicAdd(&g_all[b],  smAll[tid]);
        if (smHard[tid] != 0.f) atomicAdd(&g_hard[b], smHard[tid]);
        if (smHc[tid])          atomicAdd(&g_hcnt[b], smHc[tid]);
    }
}

// ---------------- final combine -------------------------------------------------------
__global__ void k_final(float* __restrict__ out) {
    __shared__ float sm[B];
    int i = threadIdx.x;
    float pos_sum = g_posb[i] + g_pos[i];
    float pos_cnt = (float)(g_cntb[i] + KP);
    float pl = -pos_sum / pos_cnt;
    int hc = g_hcnt[i];
    float nl = (hc > 0) ? (g_hard[i] / (float)(hc > 1 ? hc : 1))
                        : (g_all[i] / (float)((NC - 1) * KN));
    sm[i] = pl + nl;
    __syncthreads();
    for (int o = 256; o; o >>= 1) {
        if (i < o) sm[i] += sm[i + o];
        __syncthreads();
    }
    if (i == 0) out[0] = sm[0] / (float)B;
}

// ---------------- launch --------------------------------------------------------------
extern "C" void kernel_launch(void* const* d_in, const int* in_sizes, int n_in,
                              void* d_out, int out_size) {
    const float* features = (const float*)d_in[0];
    const int*   labels   = (const int*)d_in[1];
    const float* memb     = (const float*)d_in[2];
    const int*   memptr   = (const int*)d_in[3];
    float* out = (float*)d_out;

    k_init<<<(NCK + 255) / 256, 256>>>();
    k_norm<<<B, 256>>>(features);
    k_stats<<<1, B>>>(labels, memptr);
    k_batch<<<B, 128>>>(labels);
    dim3 grid((NCK + BN - 1) / BN, B / BM);
    k_gemm<<<grid, 256>>>(memb, labels);
    k_final<<<1, B>>>(out);
}

// round 4
// speedup vs baseline: 3.0325x; 1.2958x over previous
#include <cuda_runtime.h>
#include <math.h>
#include <stdint.h>

#define B   512
#define D   512
#define NC  1000
#define MM  200
#define KP  50
#define KN  20
#define NCK (NC*KP)         // 50000
#define TEMPF   0.07f
#define MARGINF 0.5f

// ---------------- device scratch (allocation-free rule: __device__ globals) -----------
__device__ float g_f[B*D];                 // normalized features
__device__ int   g_rank[B], g_gsize[B], g_first[B];
__device__ int   g_ov[NCK];                // override: batch row index or -1
__device__ float g_pos[B], g_all[B], g_hard[B], g_posb[B];
__device__ int   g_hcnt[B], g_cntb[B];

// ---------------- init: reset override table + accumulators every replay --------------
__global__ void k_init() {
    int i = blockIdx.x * blockDim.x + threadIdx.x;
    if (i < NCK) g_ov[i] = -1;
    if (i < B) {
        g_pos[i] = 0.f; g_all[i] = 0.f; g_hard[i] = 0.f; g_posb[i] = 0.f;
        g_hcnt[i] = 0;  g_cntb[i] = 0;
    }
}

// ---------------- L2 normalize rows ---------------------------------------------------
__global__ void k_norm(const float* __restrict__ x) {
    int row = blockIdx.x;
    const float* xr = x + (size_t)row * D;
    float s = 0.f;
    for (int i = threadIdx.x; i < D; i += blockDim.x) { float v = xr[i]; s += v * v; }
    __shared__ float sm[8];
    #pragma unroll
    for (int o = 16; o; o >>= 1) s += __shfl_xor_sync(0xffffffffu, s, o);
    if ((threadIdx.x & 31) == 0) sm[threadIdx.x >> 5] = s;
    __syncthreads();
    if (threadIdx.x == 0) {
        float t = 0.f;
        for (int w = 0; w < (int)(blockDim.x >> 5); w++) t += sm[w];
        sm[0] = t;
    }
    __syncthreads();
    float inv = 1.f / fmaxf(sqrtf(sm[0]), 1e-12f);
    for (int i = threadIdx.x; i < D; i += blockDim.x)
        g_f[(size_t)row * D + i] = xr[i] * inv;
}

// ---------------- label stats + override table ----------------------------------------
__global__ void k_stats(const int* __restrict__ labels, const int* __restrict__ memptr) {
    __shared__ int lab[B];
    int i = threadIdx.x;
    lab[i] = labels[i];
    __syncthreads();
    int li = lab[i];
    int r = 0, gs = 0, fi = B;
    for (int j = 0; j < B; j++) {
        if (lab[j] == li) { gs++; r += (j < i); if (j < fi) fi = j; }
    }
    g_rank[i] = r; g_gsize[i] = gs; g_first[i] = fi;
    int wp = (memptr[li] + r) % MM;
    if (wp < KP) g_ov[li * KP + wp] = i;   // unique (lab,wp) pairs -> no race
}

// ---------------- in-batch positive term (cooperative, coalesced) ---------------------
__global__ void k_batch(const int* __restrict__ labels) {
    int i = blockIdx.x;
    if (g_gsize[i] <= 1) return;           // most blocks exit (g_posb/cntb pre-zeroed)
    __shared__ float fi[D];
    __shared__ float red[8];
    int tid = threadIdx.x;
    for (int t = tid; t < D; t += 256) fi[t] = g_f[(size_t)i * D + t];
    __syncthreads();
    int li = labels[i];
    int fidx = g_first[i];
    float ssum = 0.f; int cnt = 0;
    for (int j = 0; j < B; j++) {
        if (labels[j] == li && g_rank[j] != fidx) {     // uniform per block
            const float* fj = g_f + (size_t)j * D;
            float d = 0.f;
            for (int t = tid; t < D; t += 256) d += fi[t] * fj[t];
            #pragma unroll
            for (int o = 16; o; o >>= 1) d += __shfl_xor_sync(0xffffffffu, d, o);
            if ((tid & 31) == 0) red[tid >> 5] = d;
            __syncthreads();
            if (tid == 0) {
                float v = 0.f;
                for (int w = 0; w < 8; w++) v += red[w];
                ssum += v / TEMPF; cnt++;
            }
            __syncthreads();
        }
    }
    if (tid == 0) { g_posb[i] = ssum; g_cntb[i] = cnt; }
}

// ---------------- tf32 tensor-core GEMM + fused contrastive epilogue ------------------
// Block 128x128, warp tile 64x32 (2x4 warps), BK=16, double-buffered smem.
#define BM 128
#define BN 128
#define BK 16
#define LDS_A 20           // BK + 4 pad: bank = (20*row + k) % 32 conflict-free

__device__ __forceinline__ uint32_t f2tf32(float x) {
    uint32_t r; asm("cvt.rna.tf32.f32 %0, %1;" : "=r"(r) : "f"(x)); return r;
}

__global__ __launch_bounds__(256, 2)
void k_gemm(const float* __restrict__ memb, const int* __restrict__ labels) {
    __shared__ uint32_t As[2][BM][LDS_A];
    __shared__ uint32_t Bs[2][BN][LDS_A];
    __shared__ const float* rowp[BN];
    __shared__ float smPos[BM], smAll[BM], smHard[BM];
    __shared__ int   smHc[BM];

    const int bm = blockIdx.y * BM;
    const int bn = blockIdx.x * BN;
    const int tid = threadIdx.x;
    const int lane = tid & 31, warp = tid >> 5;
    const int wm = (warp >> 2) * 64;    // warp m offset (0/64)
    const int wn = (warp & 3) * 32;     // warp n offset (0/32/64/96)
    const int g  = lane >> 2;           // groupID 0..7
    const int tg = lane & 3;            // thread-in-group 0..3

    // B row-pointer table (override -> in-batch row; else memory bank row)
    {
        int ck = bn + tid;              // covers 0..255 >= BN
        if (tid < BN) {
            const float* p = g_f;       // safe dummy for OOB ck
            if (ck < NCK) {
                int ov = g_ov[ck];
                if (ov >= 0) p = g_f + (size_t)ov * D;
                else {
                    int c = ck / KP, kk = ck - c * KP;
                    p = memb + ((size_t)c * MM + kk) * D;
                }
            }
            rowp[tid] = p;
        }
    }
    if (tid < BM) { smPos[tid] = 0.f; smAll[tid] = 0.f; smHard[tid] = 0.f; smHc[tid] = 0; }
    __syncthreads();

    // global load map: rows r0 and r0+64 for both A and B, float4 col c0 (k=4c0..4c0+3)
    const int r0 = tid >> 2, c0 = tid & 3;
    const float* Ag0 = g_f + (size_t)(bm + r0) * D + c0 * 4;
    const float* Ag1 = Ag0 + (size_t)64 * D;
    const float* Bg0 = rowp[r0] + c0 * 4;
    const float* Bg1 = rowp[r0 + 64] + c0 * 4;

    float4 pa0 = *(const float4*)Ag0;
    float4 pa1 = *(const float4*)Ag1;
    float4 pb0 = *(const float4*)Bg0;
    float4 pb1 = *(const float4*)Bg1;

    float acc[4][4][4];
    #pragma unroll
    for (int i = 0; i < 4; i++)
        #pragma unroll
        for (int j = 0; j < 4; j++)
            #pragma unroll
            for (int q = 0; q < 4; q++) acc[i][j][q] = 0.f;

    // store tile 0
    {
        uint32_t* pA0 = &As[0][r0][c0 * 4];
        uint32_t* pA1 = &As[0][r0 + 64][c0 * 4];
        uint32_t* pB0 = &Bs[0][r0][c0 * 4];
        uint32_t* pB1 = &Bs[0][r0 + 64][c0 * 4];
        pA0[0]=f2tf32(pa0.x); pA0[1]=f2tf32(pa0.y); pA0[2]=f2tf32(pa0.z); pA0[3]=f2tf32(pa0.w);
        pA1[0]=f2tf32(pa1.x); pA1[1]=f2tf32(pa1.y); pA1[2]=f2tf32(pa1.z); pA1[3]=f2tf32(pa1.w);
        pB0[0]=f2tf32(pb0.x); pB0[1]=f2tf32(pb0.y); pB0[2]=f2tf32(pb0.z); pB0[3]=f2tf32(pb0.w);
        pB1[0]=f2tf32(pb1.x); pB1[1]=f2tf32(pb1.y); pB1[2]=f2tf32(pb1.z); pB1[3]=f2tf32(pb1.w);
    }
    __syncthreads();

    const int NIT = D / BK;   // 32
    #pragma unroll 1
    for (int it = 0; it < NIT; it++) {
        int p = it & 1;
        if (it < NIT - 1) {
            int ko = (it + 1) * BK;
            pa0 = *(const float4*)(Ag0 + ko);
            pa1 = *(const float4*)(Ag1 + ko);
            pb0 = *(const float4*)(Bg0 + ko);
            pb1 = *(const float4*)(Bg1 + ko);
        }
        #pragma unroll
        for (int ks = 0; ks < BK; ks += 8) {
            uint32_t af[4][4], bf[4][2];
            #pragma unroll
            for (int mi = 0; mi < 4; mi++) {
                int mr = wm + mi * 16 + g;
                af[mi][0] = As[p][mr    ][ks + tg];
                af[mi][1] = As[p][mr + 8][ks + tg];
                af[mi][2] = As[p][mr    ][ks + tg + 4];
                af[mi][3] = As[p][mr + 8][ks + tg + 4];
            }
            #pragma unroll
            for (int nj = 0; nj < 4; nj++) {
                int nr = wn + nj * 8 + g;
                bf[nj][0] = Bs[p][nr][ks + tg];
                bf[nj][1] = Bs[p][nr][ks + tg + 4];
            }
            #pragma unroll
            for (int mi = 0; mi < 4; mi++)
                #pragma unroll
                for (int nj = 0; nj < 4; nj++) {
                    asm volatile(
                        "mma.sync.aligned.m16n8k8.row.col.f32.tf32.tf32.f32 "
                        "{%0,%1,%2,%3}, {%4,%5,%6,%7}, {%8,%9}, {%0,%1,%2,%3};\n"
                        : "+f"(acc[mi][nj][0]), "+f"(acc[mi][nj][1]),
                          "+f"(acc[mi][nj][2]), "+f"(acc[mi][nj][3])
                        : "r"(af[mi][0]), "r"(af[mi][1]), "r"(af[mi][2]), "r"(af[mi][3]),
                          "r"(bf[nj][0]), "r"(bf[nj][1]));
                }
        }
        if (it < NIT - 1) {
            int q = p ^ 1;
            uint32_t* pA0 = &As[q][r0][c0 * 4];
            uint32_t* pA1 = &As[q][r0 + 64][c0 * 4];
            uint32_t* pB0 = &Bs[q][r0][c0 * 4];
            uint32_t* pB1 = &Bs[q][r0 + 64][c0 * 4];
            pA0[0]=f2tf32(pa0.x); pA0[1]=f2tf32(pa0.y); pA0[2]=f2tf32(pa0.z); pA0[3]=f2tf32(pa0.w);
            pA1[0]=f2tf32(pa1.x); pA1[1]=f2tf32(pa1.y); pA1[2]=f2tf32(pa1.z); pA1[3]=f2tf32(pa1.w);
            pB0[0]=f2tf32(pb0.x); pB0[1]=f2tf32(pb0.y); pB0[2]=f2tf32(pb0.z); pB0[3]=f2tf32(pb0.w);
            pB1[0]=f2tf32(pb1.x); pB1[1]=f2tf32(pb1.y); pB1[2]=f2tf32(pb1.z); pB1[3]=f2tf32(pb1.w);
        }
        __syncthreads();
    }

    // ---- fused epilogue: pos / all / hard reductions (S never stored) ----
    #pragma unroll
    for (int mi = 0; mi < 4; mi++) {
        #pragma unroll
        for (int rr = 0; rr < 2; rr++) {
            int ml = wm + mi * 16 + g + rr * 8;    // local row 0..127
            int lb = labels[bm + ml];
            float pos = 0.f, alls = 0.f, hard = 0.f; int hc = 0;
            #pragma unroll
            for (int nj = 0; nj < 4; nj++) {
                #pragma unroll
                for (int q = 0; q < 2; q++) {
                    int ck = bn + wn + nj * 8 + 2 * tg + q;
                    if (ck >= NCK) continue;
                    float s = acc[mi][nj][rr * 2 + q] / TEMPF;
                    unsigned c = (unsigned)ck / KP;
                    int kk = ck - (int)c * KP;
                    if ((int)c == lb) {
                        pos += s;
                    } else if (kk < KN) {
                        alls += s;
                        if (s > MARGINF) { hard += s; hc++; }
                    }
                }
            }
            if (pos  != 0.f) atomicAdd(&smPos[ml],  pos);   // adding 0 == skipping 0
            if (alls != 0.f) atomicAdd(&smAll[ml],  alls);
            if (hard != 0.f) atomicAdd(&smHard[ml], hard);
            if (hc)          atomicAdd(&smHc[ml],   hc);
        }
    }
    __syncthreads();
    if (tid < BM) {
        int b = bm + tid;
        if (smPos[tid]  != 0.f) atomicAdd(&g_pos[b],  smPos[tid]);
        if (smAll[tid]  != 0.f) atomicAdd(&g_all[b],  smAll[tid]);
        if (smHard[tid] != 0.f) atomicAdd(&g_hard[b], smHard[tid]);
        if (smHc[tid])          atomicAdd(&g_hcnt[b], smHc[tid]);
    }
}

// ---------------- final combine -------------------------------------------------------
__global__ void k_final(float* __restrict__ out) {
    __shared__ float sm[B];
    int i = threadIdx.x;
    float pos_sum = g_posb[i] + g_pos[i];
    float pos_cnt = (float)(g_cntb[i] + KP);
    float pl = -pos_sum / pos_cnt;
    int hc = g_hcnt[i];
    float nl = (hc > 0) ? (g_hard[i] / (float)(hc > 1 ? hc : 1))
                        : (g_all[i] / (float)((NC - 1) * KN));
    sm[i] = pl + nl;
    __syncthreads();
    for (int o = 256; o; o >>= 1) {
        if (i < o) sm[i] += sm[i + o];
        __syncthreads();
    }
    if (i == 0) out[0] = sm[0] / (float)B;
}

// ---------------- launch --------------------------------------------------------------
extern "C" void kernel_launch(void* const* d_in, const int* in_sizes, int n_in,
                              void* d_out, int out_size) {
    const float* features = (const float*)d_in[0];
    const int*   labels   = (const int*)d_in[1];
    const float* memb     = (const float*)d_in[2];
    const int*   memptr   = (const int*)d_in[3];
    float* out = (float*)d_out;

    k_init<<<(NCK + 255) / 256, 256>>>();
    k_norm<<<B, 256>>>(features);
    k_stats<<<1, B>>>(labels, memptr);
    k_batch<<<B, 256>>>(labels);
    dim3 grid((NCK + BN - 1) / BN, B / BM);   // (391, 4)
    k_gemm<<<grid, 256>>>(memb, labels);
    k_final<<<1, B>>>(out);
}

// round 5
// speedup vs baseline: 5.4313x; 1.7910x over previous
#include <cuda_runtime.h>
#include <math.h>
#include <stdint.h>

#define B   512
#define D   512
#define NC  1000
#define MM  200
#define KP  50
#define KN  20
#define NCK  (NC*KP)        // 50000 (override table indexing)
#define NCKN (NC*KN)        // 20000 (GEMM columns: only k<KN needed)
#define TEMPF   0.07f
#define MARGINF 0.5f

// ---------------- device scratch ------------------------------------------------------
__device__ float g_f[B*D];                 // normalized features
__device__ int   g_rank[B], g_gsize[B], g_first[B];
__device__ int   g_ov[NCK];                // override: batch row index or -1
__device__ float g_pos[B], g_all[B], g_hard[B], g_posb[B];
__device__ int   g_hcnt[B], g_cntb[B];

// ---------------- init ----------------------------------------------------------------
__global__ void k_init() {
    int i = blockIdx.x * blockDim.x + threadIdx.x;
    if (i < NCK) g_ov[i] = -1;
    if (i < B) {
        g_pos[i] = 0.f; g_all[i] = 0.f; g_hard[i] = 0.f; g_posb[i] = 0.f;
        g_hcnt[i] = 0;  g_cntb[i] = 0;
    }
}

// ---------------- L2 normalize rows ---------------------------------------------------
__global__ void k_norm(const float* __restrict__ x) {
    int row = blockIdx.x;
    const float* xr = x + (size_t)row * D;
    float s = 0.f;
    for (int i = threadIdx.x; i < D; i += blockDim.x) { float v = xr[i]; s += v * v; }
    __shared__ float sm[8];
    #pragma unroll
    for (int o = 16; o; o >>= 1) s += __shfl_xor_sync(0xffffffffu, s, o);
    if ((threadIdx.x & 31) == 0) sm[threadIdx.x >> 5] = s;
    __syncthreads();
    if (threadIdx.x == 0) {
        float t = 0.f;
        for (int w = 0; w < (int)(blockDim.x >> 5); w++) t += sm[w];
        sm[0] = t;
    }
    __syncthreads();
    float inv = 1.f / fmaxf(sqrtf(sm[0]), 1e-12f);
    for (int i = threadIdx.x; i < D; i += blockDim.x)
        g_f[(size_t)row * D + i] = xr[i] * inv;
}

// ---------------- label stats + override table ----------------------------------------
__global__ void k_stats(const int* __restrict__ labels, const int* __restrict__ memptr) {
    __shared__ int lab[B];
    int i = threadIdx.x;
    lab[i] = labels[i];
    __syncthreads();
    int li = lab[i];
    int r = 0, gs = 0, fi = B;
    for (int j = 0; j < B; j++) {
        if (lab[j] == li) { gs++; r += (j < i); if (j < fi) fi = j; }
    }
    g_rank[i] = r; g_gsize[i] = gs; g_first[i] = fi;
    int wp = (memptr[li] + r) % MM;
    if (wp < KP) g_ov[li * KP + wp] = i;   // unique (lab,wp) pairs -> no race
}

// ---------------- shared GEMM machinery -----------------------------------------------
#define BM 128
#define BN 128
#define BK 16
#define LDS_A 20           // BK + 4 pad: bank = (20*row + k) % 32 conflict-free

__device__ __forceinline__ uint32_t f2tf32(float x) {
    uint32_t r; asm("cvt.rna.tf32.f32 %0, %1;" : "=r"(r) : "f"(x)); return r;
}

#define MMA_TF32(acc, a0, a1, a2, a3, b0, b1) \
    asm volatile("mma.sync.aligned.m16n8k8.row.col.f32.tf32.tf32.f32 " \
        "{%0,%1,%2,%3}, {%4,%5,%6,%7}, {%8,%9}, {%0,%1,%2,%3};\n" \
        : "+f"((acc)[0]), "+f"((acc)[1]), "+f"((acc)[2]), "+f"((acc)[3]) \
        : "r"(a0), "r"(a1), "r"(a2), "r"(a3), "r"(b0), "r"(b1))

// ---------------- main GEMM over k<KN columns + fused neg/pos epilogue ----------------
__global__ __launch_bounds__(256, 2)
void k_gemm(const float* __restrict__ memb, const int* __restrict__ labels) {
    __shared__ uint32_t As[2][BM][LDS_A];
    __shared__ uint32_t Bs[2][BN][LDS_A];
    __shared__ const float* rowp[BN];
    __shared__ float smPos[BM], smAll[BM], smHard[BM];
    __shared__ int   smHc[BM];

    const int bm = blockIdx.x * BM;        // M fastest -> 4 consecutive blocks share B tile
    const int bn = blockIdx.y * BN;
    const int tid = threadIdx.x;
    const int lane = tid & 31, warp = tid >> 5;
    const int wm = (warp >> 2) * 64;
    const int wn = (warp & 3) * 32;
    const int g  = lane >> 2;
    const int tg = lane & 3;

    if (tid < BN) {
        int ck = bn + tid;                 // ck = c*KN + kk, kk < KN
        const float* p = g_f;              // dummy for OOB
        if (ck < NCKN) {
            int c = ck / KN, kk = ck - c * KN;
            int ov = g_ov[c * KP + kk];
            if (ov >= 0) p = g_f + (size_t)ov * D;
            else p = memb + ((size_t)c * MM + kk) * D;
        }
        rowp[tid] = p;
    }
    if (tid < BM) { smPos[tid] = 0.f; smAll[tid] = 0.f; smHard[tid] = 0.f; smHc[tid] = 0; }
    __syncthreads();

    const int r0 = tid >> 2, c0 = tid & 3;
    const float* Ag0 = g_f + (size_t)(bm + r0) * D + c0 * 4;
    const float* Ag1 = Ag0 + (size_t)64 * D;
    const float* Bg0 = rowp[r0] + c0 * 4;
    const float* Bg1 = rowp[r0 + 64] + c0 * 4;

    float4 pa0 = *(const float4*)Ag0;
    float4 pa1 = *(const float4*)Ag1;
    float4 pb0 = *(const float4*)Bg0;
    float4 pb1 = *(const float4*)Bg1;

    float acc[4][4][4];
    #pragma unroll
    for (int i = 0; i < 4; i++)
        #pragma unroll
        for (int j = 0; j < 4; j++)
            #pragma unroll
            for (int q = 0; q < 4; q++) acc[i][j][q] = 0.f;

    {
        uint32_t* pA0 = &As[0][r0][c0 * 4];
        uint32_t* pA1 = &As[0][r0 + 64][c0 * 4];
        uint32_t* pB0 = &Bs[0][r0][c0 * 4];
        uint32_t* pB1 = &Bs[0][r0 + 64][c0 * 4];
        pA0[0]=f2tf32(pa0.x); pA0[1]=f2tf32(pa0.y); pA0[2]=f2tf32(pa0.z); pA0[3]=f2tf32(pa0.w);
        pA1[0]=f2tf32(pa1.x); pA1[1]=f2tf32(pa1.y); pA1[2]=f2tf32(pa1.z); pA1[3]=f2tf32(pa1.w);
        pB0[0]=f2tf32(pb0.x); pB0[1]=f2tf32(pb0.y); pB0[2]=f2tf32(pb0.z); pB0[3]=f2tf32(pb0.w);
        pB1[0]=f2tf32(pb1.x); pB1[1]=f2tf32(pb1.y); pB1[2]=f2tf32(pb1.z); pB1[3]=f2tf32(pb1.w);
    }
    __syncthreads();

    const int NIT = D / BK;
    #pragma unroll 1
    for (int it = 0; it < NIT; it++) {
        int p = it & 1;
        if (it < NIT - 1) {
            int ko = (it + 1) * BK;
            pa0 = *(const float4*)(Ag0 + ko);
            pa1 = *(const float4*)(Ag1 + ko);
            pb0 = *(const float4*)(Bg0 + ko);
            pb1 = *(const float4*)(Bg1 + ko);
        }
        #pragma unroll
        for (int ks = 0; ks < BK; ks += 8) {
            uint32_t af[4][4], bf[4][2];
            #pragma unroll
            for (int mi = 0; mi < 4; mi++) {
                int mr = wm + mi * 16 + g;
                af[mi][0] = As[p][mr    ][ks + tg];
                af[mi][1] = As[p][mr + 8][ks + tg];
                af[mi][2] = As[p][mr    ][ks + tg + 4];
                af[mi][3] = As[p][mr + 8][ks + tg + 4];
            }
            #pragma unroll
            for (int nj = 0; nj < 4; nj++) {
                int nr = wn + nj * 8 + g;
                bf[nj][0] = Bs[p][nr][ks + tg];
                bf[nj][1] = Bs[p][nr][ks + tg + 4];
            }
            #pragma unroll
            for (int mi = 0; mi < 4; mi++)
                #pragma unroll
                for (int nj = 0; nj < 4; nj++)
                    MMA_TF32(acc[mi][nj], af[mi][0], af[mi][1], af[mi][2], af[mi][3],
                             bf[nj][0], bf[nj][1]);
        }
        if (it < NIT - 1) {
            int q = p ^ 1;
            uint32_t* pA0 = &As[q][r0][c0 * 4];
            uint32_t* pA1 = &As[q][r0 + 64][c0 * 4];
            uint32_t* pB0 = &Bs[q][r0][c0 * 4];
            uint32_t* pB1 = &Bs[q][r0 + 64][c0 * 4];
            pA0[0]=f2tf32(pa0.x); pA0[1]=f2tf32(pa0.y); pA0[2]=f2tf32(pa0.z); pA0[3]=f2tf32(pa0.w);
            pA1[0]=f2tf32(pa1.x); pA1[1]=f2tf32(pa1.y); pA1[2]=f2tf32(pa1.z); pA1[3]=f2tf32(pa1.w);
            pB0[0]=f2tf32(pb0.x); pB0[1]=f2tf32(pb0.y); pB0[2]=f2tf32(pb0.z); pB0[3]=f2tf32(pb0.w);
            pB1[0]=f2tf32(pb1.x); pB1[1]=f2tf32(pb1.y); pB1[2]=f2tf32(pb1.z); pB1[3]=f2tf32(pb1.w);
        }
        __syncthreads();
    }

    #pragma unroll
    for (int mi = 0; mi < 4; mi++) {
        #pragma unroll
        for (int rr = 0; rr < 2; rr++) {
            int ml = wm + mi * 16 + g + rr * 8;
            int lb = labels[bm + ml];
            float pos = 0.f, alls = 0.f, hard = 0.f; int hc = 0;
            #pragma unroll
            for (int nj = 0; nj < 4; nj++) {
                #pragma unroll
                for (int q = 0; q < 2; q++) {
                    int ck = bn + wn + nj * 8 + 2 * tg + q;
                    if (ck >= NCKN) continue;
                    float s = acc[mi][nj][rr * 2 + q] / TEMPF;
                    int c = ck / KN;       // kk = ck - c*KN < KN always
                    if (c == lb) {
                        pos += s;          // own-class, k<KN part of pos
                    } else {
                        alls += s;
                        if (s > MARGINF) { hard += s; hc++; }
                    }
                }
            }
            if (pos  != 0.f) atomicAdd(&smPos[ml],  pos);
            if (alls != 0.f) atomicAdd(&smAll[ml],  alls);
            if (hard != 0.f) atomicAdd(&smHard[ml], hard);
            if (hc)          atomicAdd(&smHc[ml],   hc);
        }
    }
    __syncthreads();
    if (tid < BM) {
        int b = bm + tid;
        if (smPos[tid]  != 0.f) atomicAdd(&g_pos[b],  smPos[tid]);
        if (smAll[tid]  != 0.f) atomicAdd(&g_all[b],  smAll[tid]);
        if (smHard[tid] != 0.f) atomicAdd(&g_hard[b], smHard[tid]);
        if (smHc[tid])          atomicAdd(&g_hcnt[b], smHc[tid]);
    }
}

// ---------------- in-batch term as 512x512 tensor GEMM with fused mask ----------------
__global__ __launch_bounds__(256, 2)
void k_bgemm(const int* __restrict__ labels) {
    __shared__ uint32_t As[2][BM][LDS_A];
    __shared__ uint32_t Bs[2][BN][LDS_A];
    __shared__ float smP[BM];
    __shared__ int   smC[BM];

    const int bm = blockIdx.x * BM;
    const int bn = blockIdx.y * BN;
    const int tid = threadIdx.x;
    const int lane = tid & 31, warp = tid >> 5;
    const int wm = (warp >> 2) * 64;
    const int wn = (warp & 3) * 32;
    const int g  = lane >> 2;
    const int tg = lane & 3;

    if (tid < BM) { smP[tid] = 0.f; smC[tid] = 0; }
    __syncthreads();

    const int r0 = tid >> 2, c0 = tid & 3;
    const float* Ag0 = g_f + (size_t)(bm + r0) * D + c0 * 4;
    const float* Ag1 = Ag0 + (size_t)64 * D;
    const float* Bg0 = g_f + (size_t)(bn + r0) * D + c0 * 4;
    const float* Bg1 = Bg0 + (size_t)64 * D;

    float4 pa0 = *(const float4*)Ag0;
    float4 pa1 = *(const float4*)Ag1;
    float4 pb0 = *(const float4*)Bg0;
    float4 pb1 = *(const float4*)Bg1;

    float acc[4][4][4];
    #pragma unroll
    for (int i = 0; i < 4; i++)
        #pragma unroll
        for (int j = 0; j < 4; j++)
            #pragma unroll
            for (int q = 0; q < 4; q++) acc[i][j][q] = 0.f;

    {
        uint32_t* pA0 = &As[0][r0][c0 * 4];
        uint32_t* pA1 = &As[0][r0 + 64][c0 * 4];
        uint32_t* pB0 = &Bs[0][r0][c0 * 4];
        uint32_t* pB1 = &Bs[0][r0 + 64][c0 * 4];
        pA0[0]=f2tf32(pa0.x); pA0[1]=f2tf32(pa0.y); pA0[2]=f2tf32(pa0.z); pA0[3]=f2tf32(pa0.w);
        pA1[0]=f2tf32(pa1.x); pA1[1]=f2tf32(pa1.y); pA1[2]=f2tf32(pa1.z); pA1[3]=f2tf32(pa1.w);
        pB0[0]=f2tf32(pb0.x); pB0[1]=f2tf32(pb0.y); pB0[2]=f2tf32(pb0.z); pB0[3]=f2tf32(pb0.w);
        pB1[0]=f2tf32(pb1.x); pB1[1]=f2tf32(pb1.y); pB1[2]=f2tf32(pb1.z); pB1[3]=f2tf32(pb1.w);
    }
    __syncthreads();

    const int NIT = D / BK;
    #pragma unroll 1
    for (int it = 0; it < NIT; it++) {
        int p = it & 1;
        if (it < NIT - 1) {
            int ko = (it + 1) * BK;
            pa0 = *(const float4*)(Ag0 + ko);
            pa1 = *(const float4*)(Ag1 + ko);
            pb0 = *(const float4*)(Bg0 + ko);
            pb1 = *(const float4*)(Bg1 + ko);
        }
        #pragma unroll
        for (int ks = 0; ks < BK; ks += 8) {
            uint32_t af[4][4], bf[4][2];
            #pragma unroll
            for (int mi = 0; mi < 4; mi++) {
                int mr = wm + mi * 16 + g;
                af[mi][0] = As[p][mr    ][ks + tg];
                af[mi][1] = As[p][mr + 8][ks + tg];
                af[mi][2] = As[p][mr    ][ks + tg + 4];
                af[mi][3] = As[p][mr + 8][ks + tg + 4];
            }
            #pragma unroll
            for (int nj = 0; nj < 4; nj++) {
                int nr = wn + nj * 8 + g;
                bf[nj][0] = Bs[p][nr][ks + tg];
                bf[nj][1] = Bs[p][nr][ks + tg + 4];
            }
            #pragma unroll
            for (int mi = 0; mi < 4; mi++)
                #pragma unroll
                for (int nj = 0; nj < 4; nj++)
                    MMA_TF32(acc[mi][nj], af[mi][0], af[mi][1], af[mi][2], af[mi][3],
                             bf[nj][0], bf[nj][1]);
        }
        if (it < NIT - 1) {
            int q = p ^ 1;
            uint32_t* pA0 = &As[q][r0][c0 * 4];
            uint32_t* pA1 = &As[q][r0 + 64][c0 * 4];
            uint32_t* pB0 = &Bs[q][r0][c0 * 4];
            uint32_t* pB1 = &Bs[q][r0 + 64][c0 * 4];
            pA0[0]=f2tf32(pa0.x); pA0[1]=f2tf32(pa0.y); pA0[2]=f2tf32(pa0.z); pA0[3]=f2tf32(pa0.w);
            pA1[0]=f2tf32(pa1.x); pA1[1]=f2tf32(pa1.y); pA1[2]=f2tf32(pa1.z); pA1[3]=f2tf32(pa1.w);
            pB0[0]=f2tf32(pb0.x); pB0[1]=f2tf32(pb0.y); pB0[2]=f2tf32(pb0.z); pB0[3]=f2tf32(pb0.w);
            pB1[0]=f2tf32(pb1.x); pB1[1]=f2tf32(pb1.y); pB1[2]=f2tf32(pb1.z); pB1[3]=f2tf32(pb1.w);
        }
        __syncthreads();
    }

    // epilogue: batch mask  same-label && rank[j] != first[i] && gsize[i] > 1
    #pragma unroll
    for (int mi = 0; mi < 4; mi++) {
        #pragma unroll
        for (int rr = 0; rr < 2; rr++) {
            int ml = wm + mi * 16 + g + rr * 8;
            int i = bm + ml;
            int lb = labels[i];
            int fi = g_first[i];
            int gs = g_gsize[i];
            float ps = 0.f; int cnt = 0;
            if (gs > 1) {
                #pragma unroll
                for (int nj = 0; nj < 4; nj++) {
                    #pragma unroll
                    for (int q = 0; q < 2; q++) {
                        int j = bn + wn + nj * 8 + 2 * tg + q;
                        if (labels[j] == lb && g_rank[j] != fi) {
                            ps += acc[mi][nj][rr * 2 + q] / TEMPF;
                            cnt++;
                        }
                    }
                }
            }
            if (ps != 0.f) atomicAdd(&smP[ml], ps);
            if (cnt)       atomicAdd(&smC[ml], cnt);
        }
    }
    __syncthreads();
    if (tid < BM) {
        int b = bm + tid;
        if (smP[tid] != 0.f) atomicAdd(&g_posb[b], smP[tid]);
        if (smC[tid])        atomicAdd(&g_cntb[b], smC[tid]);
    }
}

// ---------------- own-class tail: k in [KN, KP) --------------------------------------
__global__ void k_tail(const float* __restrict__ memb, const int* __restrict__ labels) {
    int b = blockIdx.x;
    int tid = threadIdx.x;
    int lane = tid & 31, warp = tid >> 5;      // 4 warps
    __shared__ float fb[D];
    for (int t = tid; t < D; t += 128) fb[t] = g_f[(size_t)b * D + t];
    __syncthreads();
    int lb = labels[b];
    float local = 0.f;
    for (int kk = KN + warp; kk < KP; kk += 4) {
        int ov = g_ov[lb * KP + kk];
        const float* row = (ov >= 0) ? (g_f + (size_t)ov * D)
                                     : (memb + ((size_t)lb * MM + kk) * D);
        float d = 0.f;
        #pragma unroll
        for (int t = 0; t < D / 32; t++) d += fb[lane + t * 32] * row[lane + t * 32];
        #pragma unroll
        for (int o = 16; o; o >>= 1) d += __shfl_xor_sync(0xffffffffu, d, o);
        local += d;
    }
    if (lane == 0 && local != 0.f) atomicAdd(&g_pos[b], local / TEMPF);
}

// ---------------- final combine -------------------------------------------------------
__global__ void k_final(float* __restrict__ out) {
    __shared__ float sm[B];
    int i = threadIdx.x;
    float pos_sum = g_posb[i] + g_pos[i];
    float pos_cnt = (float)(g_cntb[i] + KP);
    float pl = -pos_sum / pos_cnt;
    int hc = g_hcnt[i];
    float nl = (hc > 0) ? (g_hard[i] / (float)(hc > 1 ? hc : 1))
                        : (g_all[i] / (float)((NC - 1) * KN));
    sm[i] = pl + nl;
    __syncthreads();
    for (int o = 256; o; o >>= 1) {
        if (i < o) sm[i] += sm[i + o];
        __syncthreads();
    }
    if (i == 0) out[0] = sm[0] / (float)B;
}

// ---------------- launch --------------------------------------------------------------
extern "C" void kernel_launch(void* const* d_in, const int* in_sizes, int n_in,
                              void* d_out, int out_size) {
    const float* features = (const float*)d_in[0];
    const int*   labels   = (const int*)d_in[1];
    const float* memb     = (const float*)d_in[2];
    const int*   memptr   = (const int*)d_in[3];
    float* out = (float*)d_out;

    k_init<<<(NCK + 255) / 256, 256>>>();
    k_norm<<<B, 256>>>(features);
    k_stats<<<1, B>>>(labels, memptr);
    k_bgemm<<<dim3(B / BM, B / BM), 256>>>(labels);            // (4,4) = 16 blocks
    dim3 grid(B / BM, (NCKN + BN - 1) / BN);                   // (4, 157), M fastest
    k_gemm<<<grid, 256>>>(memb, labels);
    k_tail<<<B, 128>>>(memb, labels);
    k_final<<<1, B>>>(out);
}

// round 6
// speedup vs baseline: 6.4343x; 1.1847x over previous
#include <cuda_runtime.h>
#include <math.h>
#include <stdint.h>

#define B   512
#define D   512
#define NC  1000
#define MM  200
#define KP  50
#define KN  20
#define NCKN (NC*KN)        // 20000 mem columns (only k<KN used by negatives)
#define NTOT (NCKN + B)     // 20512 = mem columns + batch columns
#define TEMPF   0.07f
#define MARGINF 0.5f

#define BM 128
#define BN 128
#define BK 16
#define LDS_A 20            // BK + 4 pad: bank = (20*row+k)%32 conflict-free
#define NTN  ((NTOT + BN - 1) / BN)   // 161
#define TILE_TOT (NTN * (B / BM))     // 644

// ---------------- device scratch ------------------------------------------------------
__device__ float g_f[B*D];
__device__ int   g_rank[B], g_gsize[B], g_first[B];
__device__ unsigned long long g_ovmask[NC];    // bit kk set -> (class,kk) overridden
__device__ int   g_ovrow[NC*KP];               // valid only where mask bit set
__device__ float g_pos[B], g_all[B], g_hard[B];
__device__ int   g_hcnt[B], g_cntb[B];
__device__ int   g_ticket;

// ---------------- prep: accum reset + normalize + stats + override mask ---------------
__global__ void k_prep(const float* __restrict__ x, const int* __restrict__ labels,
                       const int* __restrict__ memptr) {
    int bid = blockIdx.x, tid = threadIdx.x;
    if (bid < B) {
        // per-row accumulator reset + ticket reset
        if (tid == 0) {
            g_pos[bid] = 0.f; g_all[bid] = 0.f; g_hard[bid] = 0.f;
            g_hcnt[bid] = 0;  g_cntb[bid] = 0;
            if (bid == 0) g_ticket = 0;
        }
        // L2 normalize row bid
        const float* xr = x + (size_t)bid * D;
        float s = 0.f;
        for (int i = tid; i < D; i += 256) { float v = xr[i]; s += v * v; }
        __shared__ float sm[8];
        #pragma unroll
        for (int o = 16; o; o >>= 1) s += __shfl_xor_sync(0xffffffffu, s, o);
        if ((tid & 31) == 0) sm[tid >> 5] = s;
        __syncthreads();
        if (tid == 0) {
            float t = 0.f;
            for (int w = 0; w < 8; w++) t += sm[w];
            sm[0] = t;
        }
        __syncthreads();
        float inv = 1.f / fmaxf(sqrtf(sm[0]), 1e-12f);
        for (int i = tid; i < D; i += 256)
            g_f[(size_t)bid * D + i] = xr[i] * inv;
    } else {
        // stats block: 256 threads, 2 rows each
        __shared__ int lab[B];
        for (int t = tid; t < NC; t += 256) g_ovmask[t] = 0ULL;
        lab[tid] = labels[tid];
        lab[tid + 256] = labels[tid + 256];
        __syncthreads();
        #pragma unroll
        for (int ii = 0; ii < 2; ii++) {
            int i = tid + ii * 256;
            int li = lab[i];
            int r = 0, gs = 0, fi = B;
            for (int j = 0; j < B; j++) {
                int e = (lab[j] == li);
                gs += e; r += e & (j < i);
                if (e && j < fi) fi = j;
            }
            g_rank[i] = r; g_gsize[i] = gs; g_first[i] = fi;
            int wp = (memptr[li] + r) % MM;
            if (wp < KP) {
                g_ovrow[li * KP + wp] = i;          // unique (li,wp) pairs
                atomicOr(&g_ovmask[li], 1ULL << wp);
            }
        }
    }
}

// ---------------- GEMM machinery ------------------------------------------------------
__device__ __forceinline__ uint32_t f2tf32(float x) {
    uint32_t r; asm("cvt.rna.tf32.f32 %0, %1;" : "=r"(r) : "f"(x)); return r;
}
#define MMA_TF32(acc, a0, a1, a2, a3, b0, b1) \
    asm volatile("mma.sync.aligned.m16n8k8.row.col.f32.tf32.tf32.f32 " \
        "{%0,%1,%2,%3}, {%4,%5,%6,%7}, {%8,%9}, {%0,%1,%2,%3};\n" \
        : "+f"((acc)[0]), "+f"((acc)[1]), "+f"((acc)[2]), "+f"((acc)[3]) \
        : "r"(a0), "r"(a1), "r"(a2), "r"(a3), "r"(b0), "r"(b1))

// ---------------- persistent fused GEMM (mem + batch columns) -------------------------
__global__ __launch_bounds__(256, 2)
void k_gemm(const float* __restrict__ memb, const int* __restrict__ labels) {
    __shared__ uint32_t As[2][BM][LDS_A];
    __shared__ uint32_t Bs[2][BN][LDS_A];
    __shared__ const float* rowp[BN];
    __shared__ float smPos[BM], smAll[BM], smHard[BM];
    __shared__ int   smHc[BM], smCb[BM];
    __shared__ int   smTile;

    const int tid = threadIdx.x;
    const int lane = tid & 31, warp = tid >> 5;
    const int wm = (warp >> 2) * 64;
    const int wn = (warp & 3) * 32;
    const int g  = lane >> 2;
    const int tg = lane & 3;
    const int r0 = tid >> 2, c0 = tid & 3;

    for (;;) {
        if (tid == 0) smTile = atomicAdd(&g_ticket, 1);
        __syncthreads();
        const int tile = smTile;
        if (tile >= TILE_TOT) return;
        const int bm = (tile & 3) * BM;          // M fastest: B-tile L2 reuse
        const int bn = (tile >> 2) * BN;
        __syncthreads();                         // protect rowp/smem vs previous tile

        if (tid < BN) {
            int ck = bn + tid;
            const float* p = g_f;                // dummy for OOB
            if (ck < NCKN) {
                int c = ck / KN, kk = ck - c * KN;
                if ((g_ovmask[c] >> kk) & 1ULL)
                    p = g_f + (size_t)g_ovrow[c * KP + kk] * D;
                else
                    p = memb + ((size_t)c * MM + kk) * D;
            } else if (ck < NTOT) {
                p = g_f + (size_t)(ck - NCKN) * D;   // batch column
            }
            rowp[tid] = p;
        }
        if (tid < BM) { smPos[tid] = 0.f; smAll[tid] = 0.f; smHard[tid] = 0.f;
                        smHc[tid] = 0; smCb[tid] = 0; }
        __syncthreads();

        const float* Ag0 = g_f + (size_t)(bm + r0) * D + c0 * 4;
        const float* Ag1 = Ag0 + (size_t)64 * D;
        const float* Bg0 = rowp[r0] + c0 * 4;
        const float* Bg1 = rowp[r0 + 64] + c0 * 4;

        float4 pa0 = *(const float4*)Ag0;
        float4 pa1 = *(const float4*)Ag1;
        float4 pb0 = *(const float4*)Bg0;
        float4 pb1 = *(const float4*)Bg1;

        float acc[4][4][4];
        #pragma unroll
        for (int i = 0; i < 4; i++)
            #pragma unroll
            for (int j = 0; j < 4; j++)
                #pragma unroll
                for (int q = 0; q < 4; q++) acc[i][j][q] = 0.f;

        {
            uint32_t* pA0 = &As[0][r0][c0 * 4];
            uint32_t* pA1 = &As[0][r0 + 64][c0 * 4];
            uint32_t* pB0 = &Bs[0][r0][c0 * 4];
            uint32_t* pB1 = &Bs[0][r0 + 64][c0 * 4];
            pA0[0]=f2tf32(pa0.x); pA0[1]=f2tf32(pa0.y); pA0[2]=f2tf32(pa0.z); pA0[3]=f2tf32(pa0.w);
            pA1[0]=f2tf32(pa1.x); pA1[1]=f2tf32(pa1.y); pA1[2]=f2tf32(pa1.z); pA1[3]=f2tf32(pa1.w);
            pB0[0]=f2tf32(pb0.x); pB0[1]=f2tf32(pb0.y); pB0[2]=f2tf32(pb0.z); pB0[3]=f2tf32(pb0.w);
            pB1[0]=f2tf32(pb1.x); pB1[1]=f2tf32(pb1.y); pB1[2]=f2tf32(pb1.z); pB1[3]=f2tf32(pb1.w);
        }
        __syncthreads();

        const int NIT = D / BK;
        #pragma unroll 1
        for (int it = 0; it < NIT; it++) {
            int p = it & 1;
            if (it < NIT - 1) {
                int ko = (it + 1) * BK;
                pa0 = *(const float4*)(Ag0 + ko);
                pa1 = *(const float4*)(Ag1 + ko);
                pb0 = *(const float4*)(Bg0 + ko);
                pb1 = *(const float4*)(Bg1 + ko);
            }
            #pragma unroll
            for (int ks = 0; ks < BK; ks += 8) {
                uint32_t af[4][4], bf[4][2];
                #pragma unroll
                for (int mi = 0; mi < 4; mi++) {
                    int mr = wm + mi * 16 + g;
                    af[mi][0] = As[p][mr    ][ks + tg];
                    af[mi][1] = As[p][mr + 8][ks + tg];
                    af[mi][2] = As[p][mr    ][ks + tg + 4];
                    af[mi][3] = As[p][mr + 8][ks + tg + 4];
                }
                #pragma unroll
                for (int nj = 0; nj < 4; nj++) {
                    int nr = wn + nj * 8 + g;
                    bf[nj][0] = Bs[p][nr][ks + tg];
                    bf[nj][1] = Bs[p][nr][ks + tg + 4];
                }
                #pragma unroll
                for (int mi = 0; mi < 4; mi++)
                    #pragma unroll
                    for (int nj = 0; nj < 4; nj++)
                        MMA_TF32(acc[mi][nj], af[mi][0], af[mi][1], af[mi][2], af[mi][3],
                                 bf[nj][0], bf[nj][1]);
            }
            if (it < NIT - 1) {
                int q = p ^ 1;
                uint32_t* pA0 = &As[q][r0][c0 * 4];
                uint32_t* pA1 = &As[q][r0 + 64][c0 * 4];
                uint32_t* pB0 = &Bs[q][r0][c0 * 4];
                uint32_t* pB1 = &Bs[q][r0 + 64][c0 * 4];
                pA0[0]=f2tf32(pa0.x); pA0[1]=f2tf32(pa0.y); pA0[2]=f2tf32(pa0.z); pA0[3]=f2tf32(pa0.w);
                pA1[0]=f2tf32(pa1.x); pA1[1]=f2tf32(pa1.y); pA1[2]=f2tf32(pa1.z); pA1[3]=f2tf32(pa1.w);
                pB0[0]=f2tf32(pb0.x); pB0[1]=f2tf32(pb0.y); pB0[2]=f2tf32(pb0.z); pB0[3]=f2tf32(pb0.w);
                pB1[0]=f2tf32(pb1.x); pB1[1]=f2tf32(pb1.y); pB1[2]=f2tf32(pb1.z); pB1[3]=f2tf32(pb1.w);
            }
            __syncthreads();
        }

        // ---- fused epilogue: mem columns (pos/all/hard) + batch columns (pos/cnt) ----
        #pragma unroll
        for (int mi = 0; mi < 4; mi++) {
            #pragma unroll
            for (int rr = 0; rr < 2; rr++) {
                int ml = wm + mi * 16 + g + rr * 8;
                int i = bm + ml;
                int lb = labels[i];
                int fi = g_first[i];
                int gs = g_gsize[i];
                float pos = 0.f, alls = 0.f, hard = 0.f; int hc = 0, cb = 0;
                #pragma unroll
                for (int nj = 0; nj < 4; nj++) {
                    #pragma unroll
                    for (int q = 0; q < 2; q++) {
                        int ck = bn + wn + nj * 8 + 2 * tg + q;
                        float s = acc[mi][nj][rr * 2 + q] / TEMPF;
                        if (ck < NCKN) {
                            int c = ck / KN;
                            if (c == lb) {
                                pos += s;
                            } else {
                                alls += s;
                                if (s > MARGINF) { hard += s; hc++; }
                            }
                        } else if (ck < NTOT) {
                            int j = ck - NCKN;
                            if (gs > 1 && labels[j] == lb && g_rank[j] != fi) {
                                pos += s; cb++;
                            }
                        }
                    }
                }
                if (pos  != 0.f) atomicAdd(&smPos[ml],  pos);   // add-0 == skip-0
                if (alls != 0.f) atomicAdd(&smAll[ml],  alls);
                if (hard != 0.f) atomicAdd(&smHard[ml], hard);
                if (hc)          atomicAdd(&smHc[ml],   hc);
                if (cb)          atomicAdd(&smCb[ml],   cb);
            }
        }
        __syncthreads();
        if (tid < BM) {
            int b = bm + tid;
            if (smPos[tid]  != 0.f) atomicAdd(&g_pos[b],  smPos[tid]);
            if (smAll[tid]  != 0.f) atomicAdd(&g_all[b],  smAll[tid]);
            if (smHard[tid] != 0.f) atomicAdd(&g_hard[b], smHard[tid]);
            if (smHc[tid])          atomicAdd(&g_hcnt[b], smHc[tid]);
            if (smCb[tid])          atomicAdd(&g_cntb[b], smCb[tid]);
        }
    }
}

// ---------------- own-class tail: k in [KN, KP) ---------------------------------------
__global__ void k_tail(const float* __restrict__ memb, const int* __restrict__ labels) {
    int b = blockIdx.x;
    int tid = threadIdx.x;
    int lane = tid & 31, warp = tid >> 5;      // 4 warps
    __shared__ float fb[D];
    for (int t = tid; t < D; t += 128) fb[t] = g_f[(size_t)b * D + t];
    __syncthreads();
    int lb = labels[b];
    unsigned long long mask = g_ovmask[lb];
    float local = 0.f;
    for (int kk = KN + warp; kk < KP; kk += 4) {
        const float* row = ((mask >> kk) & 1ULL)
                         ? (g_f + (size_t)g_ovrow[lb * KP + kk] * D)
                         : (memb + ((size_t)lb * MM + kk) * D);
        float d = 0.f;
        #pragma unroll
        for (int t = 0; t < D / 32; t++) d += fb[lane + t * 32] * row[lane + t * 32];
        #pragma unroll
        for (int o = 16; o; o >>= 1) d += __shfl_xor_sync(0xffffffffu, d, o);
        local += d;
    }
    if (lane == 0 && local != 0.f) atomicAdd(&g_pos[b], local / TEMPF);
}

// ---------------- final combine -------------------------------------------------------
__global__ void k_final(float* __restrict__ out) {
    __shared__ float sm[B];
    int i = threadIdx.x;
    float pos_sum = g_pos[i];
    float pos_cnt = (float)(g_cntb[i] + KP);
    float pl = -pos_sum / pos_cnt;
    int hc = g_hcnt[i];
    float nl = (hc > 0) ? (g_hard[i] / (float)(hc > 1 ? hc : 1))
                        : (g_all[i] / (float)((NC - 1) * KN));
    sm[i] = pl + nl;
    __syncthreads();
    for (int o = 256; o; o >>= 1) {
        if (i < o) sm[i] += sm[i + o];
        __syncthreads();
    }
    if (i == 0) out[0] = sm[0] / (float)B;
}

// ---------------- launch --------------------------------------------------------------
extern "C" void kernel_launch(void* const* d_in, const int* in_sizes, int n_in,
                              void* d_out, int out_size) {
    const float* features = (const float*)d_in[0];
    const int*   labels   = (const int*)d_in[1];
    const float* memb     = (const float*)d_in[2];
    const int*   memptr   = (const int*)d_in[3];
    float* out = (float*)d_out;

    k_prep<<<B + 1, 256>>>(features, labels, memptr);
    k_gemm<<<296, 256>>>(memb, labels);        // persistent, work-stealing
    k_tail<<<B, 128>>>(memb, labels);
    k_final<<<1, B>>>(out);
}

// round 7
// speedup vs baseline: 6.8721x; 1.0680x over previous
#include <cuda_runtime.h>
#include <math.h>
#include <stdint.h>

#define B   512
#define D   512
#define NC  1000
#define MM  200
#define KP  50
#define KN  20
#define NCKN (NC*KN)        // 20000 mem columns (only k<KN used by negatives)
#define NTOT (NCKN + B)     // 20512 = mem columns + batch columns
#define TEMPF   0.07f
#define MARGINF 0.5f

#define BM 128
#define BN 128
#define BK 16               // 16 bf16 elements per stage = one m16n8k16 step
#define LDS_W 12            // 8 uint32 (bf16x2) + 4 pad: (12*row+j)%32 conflict-free
#define NTN  ((NTOT + BN - 1) / BN)   // 161
#define TILE_TOT (NTN * (B / BM))     // 644

// ---------------- device scratch ------------------------------------------------------
__device__ float g_f[B*D];
__device__ int   g_rank[B], g_gsize[B], g_first[B];
__device__ unsigned long long g_ovmask[NC];    // bit kk set -> (class,kk) overridden
__device__ int   g_ovrow[NC*KP];               // valid only where mask bit set
__device__ float g_pos[B], g_all[B], g_hard[B];
__device__ int   g_hcnt[B], g_cntb[B];
__device__ int   g_ticket;

// ---------------- prep: accum reset + normalize + stats + override mask ---------------
__global__ void k_prep(const float* __restrict__ x, const int* __restrict__ labels,
                       const int* __restrict__ memptr) {
    int bid = blockIdx.x, tid = threadIdx.x;
    if (bid < B) {
        if (tid == 0) {
            g_pos[bid] = 0.f; g_all[bid] = 0.f; g_hard[bid] = 0.f;
            g_hcnt[bid] = 0;  g_cntb[bid] = 0;
            if (bid == 0) g_ticket = 0;
        }
        const float* xr = x + (size_t)bid * D;
        float s = 0.f;
        for (int i = tid; i < D; i += 256) { float v = xr[i]; s += v * v; }
        __shared__ float sm[8];
        #pragma unroll
        for (int o = 16; o; o >>= 1) s += __shfl_xor_sync(0xffffffffu, s, o);
        if ((tid & 31) == 0) sm[tid >> 5] = s;
        __syncthreads();
        if (tid == 0) {
            float t = 0.f;
            for (int w = 0; w < 8; w++) t += sm[w];
            sm[0] = t;
        }
        __syncthreads();
        float inv = 1.f / fmaxf(sqrtf(sm[0]), 1e-12f);
        for (int i = tid; i < D; i += 256)
            g_f[(size_t)bid * D + i] = xr[i] * inv;
    } else {
        __shared__ int lab[B];
        for (int t = tid; t < NC; t += 256) g_ovmask[t] = 0ULL;
        lab[tid] = labels[tid];
        lab[tid + 256] = labels[tid + 256];
        __syncthreads();
        #pragma unroll
        for (int ii = 0; ii < 2; ii++) {
            int i = tid + ii * 256;
            int li = lab[i];
            int r = 0, gs = 0, fi = B;
            for (int j = 0; j < B; j++) {
                int e = (lab[j] == li);
                gs += e; r += e & (j < i);
                if (e && j < fi) fi = j;
            }
            g_rank[i] = r; g_gsize[i] = gs; g_first[i] = fi;
            int wp = (memptr[li] + r) % MM;
            if (wp < KP) {
                g_ovrow[li * KP + wp] = i;          // unique (li,wp) pairs
                atomicOr(&g_ovmask[li], 1ULL << wp);
            }
        }
    }
}

// ---------------- GEMM machinery ------------------------------------------------------
__device__ __forceinline__ uint32_t pack_bf16x2(float lo, float hi) {
    uint32_t r;
    asm("cvt.rn.bf16x2.f32 %0, %1, %2;" : "=r"(r) : "f"(hi), "f"(lo));  // d.lo=convert(b)
    return r;
}
#define MMA_BF16(acc, a0, a1, a2, a3, b0, b1) \
    asm volatile("mma.sync.aligned.m16n8k16.row.col.f32.bf16.bf16.f32 " \
        "{%0,%1,%2,%3}, {%4,%5,%6,%7}, {%8,%9}, {%0,%1,%2,%3};\n" \
        : "+f"((acc)[0]), "+f"((acc)[1]), "+f"((acc)[2]), "+f"((acc)[3]) \
        : "r"(a0), "r"(a1), "r"(a2), "r"(a3), "r"(b0), "r"(b1))

// ---------------- persistent fused bf16 GEMM (mem + batch columns) --------------------
__global__ __launch_bounds__(256, 2)
void k_gemm(const float* __restrict__ memb, const int* __restrict__ labels) {
    __shared__ uint32_t As[2][BM][LDS_W];
    __shared__ uint32_t Bs[2][BN][LDS_W];
    __shared__ const float* rowp[BN];
    __shared__ float smPos[BM], smAll[BM], smHard[BM];
    __shared__ int   smHc[BM], smCb[BM];
    __shared__ int   smTile;

    const int tid = threadIdx.x;
    const int lane = tid & 31, warp = tid >> 5;
    const int wm = (warp >> 2) * 64;
    const int wn = (warp & 3) * 32;
    const int g  = lane >> 2;
    const int tg = lane & 3;
    const int r0 = tid >> 1;            // 0..127: row for both A and B tiles
    const int h0 = (tid & 1) * 8;       // float offset 0/8 within the 16-float stage
    const int u0 = (tid & 1) * 4;       // uint32 offset 0/4 in smem row

    for (;;) {
        if (tid == 0) smTile = atomicAdd(&g_ticket, 1);
        __syncthreads();
        const int tile = smTile;
        if (tile >= TILE_TOT) return;
        const int bm = (tile & 3) * BM;          // M fastest: B-tile L2 reuse
        const int bn = (tile >> 2) * BN;
        __syncthreads();                         // protect rowp/smem vs previous tile

        if (tid < BN) {
            int ck = bn + tid;
            const float* p = g_f;                // dummy for OOB
            if (ck < NCKN) {
                int c = ck / KN, kk = ck - c * KN;
                if ((g_ovmask[c] >> kk) & 1ULL)
                    p = g_f + (size_t)g_ovrow[c * KP + kk] * D;
                else
                    p = memb + ((size_t)c * MM + kk) * D;
            } else if (ck < NTOT) {
                p = g_f + (size_t)(ck - NCKN) * D;   // batch column
            }
            rowp[tid] = p;
        }
        if (tid < BM) { smPos[tid] = 0.f; smAll[tid] = 0.f; smHard[tid] = 0.f;
                        smHc[tid] = 0; smCb[tid] = 0; }
        __syncthreads();

        const float* Ag = g_f + (size_t)(bm + r0) * D + h0;
        const float* Bg = rowp[r0] + h0;

        float4 pa0 = *(const float4*)Ag;
        float4 pa1 = *(const float4*)(Ag + 4);
        float4 pb0 = *(const float4*)Bg;
        float4 pb1 = *(const float4*)(Bg + 4);

        float acc[4][4][4];
        #pragma unroll
        for (int i = 0; i < 4; i++)
            #pragma unroll
            for (int j = 0; j < 4; j++)
                #pragma unroll
                for (int q = 0; q < 4; q++) acc[i][j][q] = 0.f;

        {
            uint32_t* pA = &As[0][r0][u0];
            uint32_t* pB = &Bs[0][r0][u0];
            pA[0] = pack_bf16x2(pa0.x, pa0.y); pA[1] = pack_bf16x2(pa0.z, pa0.w);
            pA[2] = pack_bf16x2(pa1.x, pa1.y); pA[3] = pack_bf16x2(pa1.z, pa1.w);
            pB[0] = pack_bf16x2(pb0.x, pb0.y); pB[1] = pack_bf16x2(pb0.z, pb0.w);
            pB[2] = pack_bf16x2(pb1.x, pb1.y); pB[3] = pack_bf16x2(pb1.z, pb1.w);
        }
        __syncthreads();

        const int NIT = D / BK;     // 32 stages, one m16n8k16 step each
        #pragma unroll 1
        for (int it = 0; it < NIT; it++) {
            int p = it & 1;
            if (it < NIT - 1) {
                int ko = (it + 1) * BK;
                pa0 = *(const float4*)(Ag + ko);
                pa1 = *(const float4*)(Ag + ko + 4);
                pb0 = *(const float4*)(Bg + ko);
                pb1 = *(const float4*)(Bg + ko + 4);
            }
            {
                uint32_t af[4][4], bf[4][2];
                #pragma unroll
                for (int mi = 0; mi < 4; mi++) {
                    int mr = wm + mi * 16 + g;
                    af[mi][0] = As[p][mr    ][tg];
                    af[mi][1] = As[p][mr + 8][tg];
                    af[mi][2] = As[p][mr    ][tg + 4];
                    af[mi][3] = As[p][mr + 8][tg + 4];
                }
                #pragma unroll
                for (int nj = 0; nj < 4; nj++) {
                    int nr = wn + nj * 8 + g;
                    bf[nj][0] = Bs[p][nr][tg];
                    bf[nj][1] = Bs[p][nr][tg + 4];
                }
                #pragma unroll
                for (int mi = 0; mi < 4; mi++)
                    #pragma unroll
                    for (int nj = 0; nj < 4; nj++)
                        MMA_BF16(acc[mi][nj], af[mi][0], af[mi][1], af[mi][2], af[mi][3],
                                 bf[nj][0], bf[nj][1]);
            }
            if (it < NIT - 1) {
                int q = p ^ 1;
                uint32_t* pA = &As[q][r0][u0];
                uint32_t* pB = &Bs[q][r0][u0];
                pA[0] = pack_bf16x2(pa0.x, pa0.y); pA[1] = pack_bf16x2(pa0.z, pa0.w);
                pA[2] = pack_bf16x2(pa1.x, pa1.y); pA[3] = pack_bf16x2(pa1.z, pa1.w);
                pB[0] = pack_bf16x2(pb0.x, pb0.y); pB[1] = pack_bf16x2(pb0.z, pb0.w);
                pB[2] = pack_bf16x2(pb1.x, pb1.y); pB[3] = pack_bf16x2(pb1.z, pb1.w);
            }
            __syncthreads();
        }

        // ---- fused epilogue: mem columns (pos/all/hard) + batch columns (pos/cnt) ----
        #pragma unroll
        for (int mi = 0; mi < 4; mi++) {
            #pragma unroll
            for (int rr = 0; rr < 2; rr++) {
                int ml = wm + mi * 16 + g + rr * 8;
                int i = bm + ml;
                int lb = labels[i];
                int fi = g_first[i];
                int gs = g_gsize[i];
                float pos = 0.f, alls = 0.f, hard = 0.f; int hc = 0, cb = 0;
                #pragma unroll
                for (int nj = 0; nj < 4; nj++) {
                    #pragma unroll
                    for (int q = 0; q < 2; q++) {
                        int ck = bn + wn + nj * 8 + 2 * tg + q;
                        float s = acc[mi][nj][rr * 2 + q] / TEMPF;
                        if (ck < NCKN) {
                            int c = ck / KN;
                            if (c == lb) {
                                pos += s;
                            } else {
                                alls += s;
                                if (s > MARGINF) { hard += s; hc++; }
                            }
                        } else if (ck < NTOT) {
                            int j = ck - NCKN;
                            if (gs > 1 && labels[j] == lb && g_rank[j] != fi) {
                                pos += s; cb++;
                            }
                        }
                    }
                }
                if (pos  != 0.f) atomicAdd(&smPos[ml],  pos);   // add-0 == skip-0
                if (alls != 0.f) atomicAdd(&smAll[ml],  alls);
                if (hard != 0.f) atomicAdd(&smHard[ml], hard);
                if (hc)          atomicAdd(&smHc[ml],   hc);
                if (cb)          atomicAdd(&smCb[ml],   cb);
            }
        }
        __syncthreads();
        if (tid < BM) {
            int b = bm + tid;
            if (smPos[tid]  != 0.f) atomicAdd(&g_pos[b],  smPos[tid]);
            if (smAll[tid]  != 0.f) atomicAdd(&g_all[b],  smAll[tid]);
            if (smHard[tid] != 0.f) atomicAdd(&g_hard[b], smHard[tid]);
            if (smHc[tid])          atomicAdd(&g_hcnt[b], smHc[tid]);
            if (smCb[tid])          atomicAdd(&g_cntb[b], smCb[tid]);
        }
    }
}

// ---------------- own-class tail: k in [KN, KP) ---------------------------------------
__global__ void k_tail(const float* __restrict__ memb, const int* __restrict__ labels) {
    int b = blockIdx.x;
    int tid = threadIdx.x;
    int lane = tid & 31, warp = tid >> 5;      // 4 warps
    __shared__ float fb[D];
    for (int t = tid; t < D; t += 128) fb[t] = g_f[(size_t)b * D + t];
    __syncthreads();
    int lb = labels[b];
    unsigned long long mask = g_ovmask[lb];
    float local = 0.f;
    for (int kk = KN + warp; kk < KP; kk += 4) {
        const float* row = ((mask >> kk) & 1ULL)
                         ? (g_f + (size_t)g_ovrow[lb * KP + kk] * D)
                         : (memb + ((size_t)lb * MM + kk) * D);
        float d = 0.f;
        #pragma unroll
        for (int t = 0; t < D / 32; t++) d += fb[lane + t * 32] * row[lane + t * 32];
        #pragma unroll
        for (int o = 16; o; o >>= 1) d += __shfl_xor_sync(0xffffffffu, d, o);
        local += d;
    }
    if (lane == 0 && local != 0.f) atomicAdd(&g_pos[b], local / TEMPF);
}

// ---------------- final combine -------------------------------------------------------
__global__ void k_final(float* __restrict__ out) {
    __shared__ float sm[B];
    int i = threadIdx.x;
    float pos_sum = g_pos[i];
    float pos_cnt = (float)(g_cntb[i] + KP);
    float pl = -pos_sum / pos_cnt;
    int hc = g_hcnt[i];
    float nl = (hc > 0) ? (g_hard[i] / (float)(hc > 1 ? hc : 1))
                        : (g_all[i] / (float)((NC - 1) * KN));
    sm[i] = pl + nl;
    __syncthreads();
    for (int o = 256; o; o >>= 1) {
        if (i < o) sm[i] += sm[i + o];
        __syncthreads();
    }
    if (i == 0) out[0] = sm[0] / (float)B;
}

// ---------------- launch --------------------------------------------------------------
extern "C" void kernel_launch(void* const* d_in, const int* in_sizes, int n_in,
                              void* d_out, int out_size) {
    const float* features = (const float*)d_in[0];
    const int*   labels   = (const int*)d_in[1];
    const float* memb     = (const float*)d_in[2];
    const int*   memptr   = (const int*)d_in[3];
    float* out = (float*)d_out;

    k_prep<<<B + 1, 256>>>(features, labels, memptr);
    k_gemm<<<296, 256>>>(memb, labels);        // persistent, work-stealing
    k_tail<<<B, 128>>>(memb, labels);
    k_final<<<1, B>>>(out);
}